// round 16
// baseline (speedup 1.0000x reference)
#include <cuda_runtime.h>
#include <cuda_bf16.h>
#include <cstdint>

static constexpr int N_ROWS = 4096;
static constexpr int N_COLS = 32000;
static constexpr int SEGS   = 10;              // segments per row
static constexpr int SEG4   = (N_COLS / 4) / SEGS;  // 800 float4 per segment
static constexpr int TPB    = 160;             // 800 = 160 * 5 (one 5-load batch)
static constexpr int BATCH  = 5;
static constexpr int PREP_BLK = 32;            // prep blocks (run first, overlap)
static constexpr int SBLK   = N_ROWS * SEGS;   // 40960 streaming blocks
static constexpr int FTPB   = 1024;            // final kernel threads

// Scratch (no device mallocs allowed)
__device__ float g_seg_sum[N_ROWS * SEGS];
__device__ float g_xt[N_ROWS];

// ---------------------------------------------------------------------------
// Fast exp: Schraudolph bit-trick + cubic mantissa correction.
// Max rel error ~5.5e-4, near-zero mean. No MUFU in the hot loop.
// ---------------------------------------------------------------------------
__device__ __forceinline__ float fast_exp_term(float x) {
    float v  = fmaf(x, 12102203.0f, 1065353216.0f);
    int   iv = (int)v;
    float a  = __int_as_float(iv);
    float u  = (float)(iv & 0x007fffff);           // mantissa bits as float
    float p  = fmaf(u, fmaf(u, fmaf(u, -1.71524e-22f, 5.43943e-15f),
                            -3.35594e-8f), 1.0f);
    return a * p;
}

// ---------------------------------------------------------------------------
// Kernel 1: blocks 0..31 = PREP (dtype detection + target xt gather, their
// DRAM latency overlaps the stream); blocks 32.. = STREAM (1/10-row segments,
// 160 thr x 5 loads = 800 float4, exactly one front-batched body -> small
// blocks shrink the ragged-edge loss R14 identified).
//
// Dtype detection: int32 data misread as int64 decodes outside [0,32000)
// for nearly every 8-byte slot; first 2048 slots = 16 KB = int32 buf size.
// __ldcs on the stream: data read exactly once (evict-first).
// ---------------------------------------------------------------------------
__global__ void __launch_bounds__(TPB)
sumexp_prep_kernel(const float* __restrict__ input, const void* __restrict__ tgt)
{
    if (blockIdx.x < PREP_BLK) {
        const int tid = threadIdx.x;
        const long long* t64 = (const long long*)tgt;

        int ok = 1;
        if (tid < 128) {
            #pragma unroll
            for (int k = 0; k < 16; k++) {          // 128*16 = 2048 slots
                long long v = t64[tid + k * 128];
                if (v < 0 || v >= (long long)N_COLS) ok = 0;
            }
        }
        const int is64 = __syncthreads_and(ok);

        if (tid < 128) {
            const int row = blockIdx.x * 128 + tid;  // 32*128 = 4096 rows
            long long t = is64 ? t64[row] : (long long)(((const int*)tgt)[row]);
            g_xt[row] = __ldg(input + (size_t)row * N_COLS + (size_t)t);
        }
        return;
    }

    const int sid = blockIdx.x - PREP_BLK;
    const int row = sid / SEGS;
    const int seg = sid - row * SEGS;
    const float4* __restrict__ p =
        reinterpret_cast<const float4*>(input) + (size_t)row * (N_COLS / 4) + seg * SEG4;

    float4 v[BATCH];
    #pragma unroll
    for (int k = 0; k < BATCH; k++)
        v[k] = __ldcs(p + threadIdx.x + k * TPB);

    float s0 = 0.f, s1 = 0.f, s2 = 0.f, s3 = 0.f;
    #pragma unroll
    for (int k = 0; k < BATCH; k++) {
        s0 += fast_exp_term(v[k].x);
        s1 += fast_exp_term(v[k].y);
        s2 += fast_exp_term(v[k].z);
        s3 += fast_exp_term(v[k].w);
    }
    float s = (s0 + s1) + (s2 + s3);

    #pragma unroll
    for (int o = 16; o > 0; o >>= 1)
        s += __shfl_xor_sync(0xffffffffu, s, o);

    __shared__ float warp_s[TPB / 32];
    if ((threadIdx.x & 31) == 0) warp_s[threadIdx.x >> 5] = s;
    __syncthreads();

    if (threadIdx.x == 0) {
        float S = 0.f;
        #pragma unroll
        for (int w = 0; w < TPB / 32; w++) S += warp_s[w];
        g_seg_sum[sid] = S;
    }
}

// ---------------------------------------------------------------------------
// Kernel 2 (one block, 1024 threads, 4 rows/thread): everything L2-resident
// (g_seg_sum + g_xt just written). Fixed-order 10-segment sum per row ->
// deterministic. MUFU logf/expf only here (4 rows/thread).
// ---------------------------------------------------------------------------
__global__ void __launch_bounds__(FTPB)
focal_finish_kernel(float* __restrict__ out)
{
    const int tid = threadIdx.x;

    float acc = 0.f;
    #pragma unroll
    for (int k = 0; k < N_ROWS / FTPB; k++) {
        const int row = tid + k * FTPB;
        float S = 0.f;
        #pragma unroll
        for (int j = 0; j < SEGS; j++)
            S += g_seg_sum[row * SEGS + j];        // fixed order
        float xt    = g_xt[row];
        float logpt = xt - logf(S);
        float pt    = expf(logpt);
        float omp   = 1.0f - pt;
        // gamma: 5 iff pt < 0.2, else 3 (GAMMA_SELF == GAMMA_LT_05 == 3)
        float w3    = omp * omp * omp;
        float wgt   = (pt < 0.2f) ? w3 * omp * omp : w3;
        acc += -wgt * logpt;
    }

    #pragma unroll
    for (int o = 16; o > 0; o >>= 1)
        acc += __shfl_xor_sync(0xffffffffu, acc, o);

    __shared__ float warp_s[FTPB / 32];
    if ((tid & 31) == 0) warp_s[tid >> 5] = acc;
    __syncthreads();

    if (tid == 0) {
        float T = 0.f;
        #pragma unroll
        for (int w = 0; w < FTPB / 32; w++) T += warp_s[w];
        out[0] = T;
    }
}

extern "C" void kernel_launch(void* const* d_in, const int* in_sizes, int n_in,
                              void* d_out, int out_size) {
    const float* input = (const float*)d_in[0];
    const void*  tgt   = d_in[1];
    (void)in_sizes; (void)n_in; (void)out_size;

    sumexp_prep_kernel<<<PREP_BLK + SBLK, TPB>>>(input, tgt);
    focal_finish_kernel<<<1, FTPB>>>((float*)d_out);
}